// round 1
// baseline (speedup 1.0000x reference)
#include <cuda_runtime.h>
#include <math.h>

// Problem constants (fixed shapes from reference setup_inputs)
#define NB 16      // batch n
#define TT 12      // time t
#define NN 64      // nodes N
#define CC 64      // in channels
#define OO 64      // out channels
#define LRELU_ALPHA 0.2f

// Scratch (no cudaMalloc allowed): h and the three collapsed dot-product tables
__device__ float d_h  [NB * TT * NN * OO];     // 3 MB
__device__ float d_g1 [NB * TT * NN];          // dot(h, a_lo + a_hi)
__device__ float d_g2a[NB * TT * NN];          // dot(h, a[0:64])
__device__ float d_g2b[NB * TT * NN];          // dot(h, a[64:128])

// ---------------------------------------------------------------------------
// Kernel 1: one block per (n, s).  h[n,s] = inp[n,s] @ W  (64x64x64), plus
// the three per-row dot products g1/g2a/g2b that the score tensor collapses to.
// ---------------------------------------------------------------------------
__global__ __launch_bounds__(256) void gat_k1(
    const float* __restrict__ inp,   // [NB,TT,NN,CC]
    const float* __restrict__ W,     // [CC,OO]
    const float* __restrict__ a)     // [2*OO]
{
    __shared__ float s_in[64 * 65];   // inp tile (padded), later reused for h
    __shared__ float s_W [64 * 64];
    __shared__ float s_alo[64], s_ahi[64], s_A1[64];

    const int tid = threadIdx.x;
    const int blk = blockIdx.x;                  // = n*TT + s
    const float* ip = inp + (size_t)blk * 4096;

    for (int idx = tid; idx < 4096; idx += 256) {
        s_in[(idx >> 6) * 65 + (idx & 63)] = ip[idx];
        s_W[idx] = W[idx];
    }
    if (tid < 64) {
        float lo = a[tid], hi = a[tid + 64];
        s_alo[tid] = lo; s_ahi[tid] = hi; s_A1[tid] = lo + hi;
    }
    __syncthreads();

    // GEMM: thread (v = tid>>2, quad = tid&3) computes h[v][quad + 4*i], i<16
    const int v = tid >> 2, quad = tid & 3;
    float acc[16];
#pragma unroll
    for (int i = 0; i < 16; i++) acc[i] = 0.f;
    for (int k = 0; k < 64; k++) {
        const float av = s_in[v * 65 + k];
#pragma unroll
        for (int i = 0; i < 16; i++)
            acc[i] = fmaf(av, s_W[k * 64 + quad + 4 * i], acc[i]);
    }
    __syncthreads();                 // done reading s_in as inp
#pragma unroll
    for (int i = 0; i < 16; i++) s_in[v * 65 + quad + 4 * i] = acc[i];
    __syncthreads();                 // s_in now holds h

    // Coalesced h -> global
    float* hp = d_h + (size_t)blk * 4096;
    for (int idx = tid; idx < 4096; idx += 256)
        hp[idx] = s_in[(idx >> 6) * 65 + (idx & 63)];

    // Three dot products per row (192 threads: u = tid/3, which = tid%3)
    if (tid < 192) {
        const int u = tid / 3, c = tid - 3 * u;
        const float* av = (c == 0) ? s_A1 : (c == 1 ? s_alo : s_ahi);
        float s = 0.f;
        for (int k = 0; k < 64; k++) s = fmaf(s_in[u * 65 + k], av[k], s);
        float* gp = (c == 0) ? d_g1 : (c == 1 ? d_g2a : d_g2b);
        gp[blk * 64 + u] = s;
    }
}

// ---------------------------------------------------------------------------
// Kernel 2: one block per (n, ti).  Build e from the g tables, softmax over w,
// h_prime = att @ h[n,ti], elu.  Writes both outputs.
// ---------------------------------------------------------------------------
__global__ __launch_bounds__(256) void gat_k2(
    float* __restrict__ out_elu,     // [NB,TT,NN,OO]
    float* __restrict__ out_att,     // [NB,TT,NN,NN] (may be unused)
    int write_att)
{
    __shared__ float s_h  [64 * 65];   // h[n,ti] (padded)
    __shared__ float s_att[64 * 65];   // attention, later reused as elu staging
    __shared__ float s_g  [3 * 128];   // g tables for the 2 source times

    const int tid = threadIdx.x;
    const int blk = blockIdx.x;                  // = n*TT + ti
    const int n = blk / TT, ti = blk - n * TT;

    const float* hp = d_h + (size_t)blk * 4096;
    for (int idx = tid; idx < 4096; idx += 256)
        s_h[(idx >> 6) * 65 + (idx & 63)] = hp[idx];

    if (tid < 128) {
        if (ti < 6) {
            s_g[tid] = d_g1[(n * TT + 2 * ti) * 64 + tid];      // rows 2ti, 2ti+1
        } else {
            const int base = (n * TT + 2 * (ti - 6)) * 64;
            s_g[128 + tid] = d_g2a[base + tid];
            s_g[256 + tid] = d_g2b[base + tid];
        }
    }
    __syncthreads();

    // Softmax: warp wp handles rows v = wp*8 .. wp*8+7; lane owns w=ln, w=ln+32
    const int warp = tid >> 5, ln = tid & 31;
    for (int r = 0; r < 8; r++) {
        const int v  = warp * 8 + r;
        const int vb = (v >= 32) ? 1 : 0;
        float e0, e1;
        if (ti < 6) {
            const int base = vb * 64 + 2 * (v & 31);
            e0 = s_g[base + 0];          // w <  32
            e1 = s_g[base + 1];          // w >= 32
        } else {
            const int off = vb * 64 + 2 * ln;    // w & 31 == ln for both halves
            const float e = s_g[128 + off] + s_g[256 + off + 1];
            e0 = e; e1 = e;
        }
        e0 = (e0 > 0.f) ? e0 : LRELU_ALPHA * e0;
        e1 = (e1 > 0.f) ? e1 : LRELU_ALPHA * e1;

        float m = fmaxf(e0, e1);
#pragma unroll
        for (int o = 16; o; o >>= 1) m = fmaxf(m, __shfl_xor_sync(0xffffffffu, m, o));
        const float p0 = __expf(e0 - m), p1 = __expf(e1 - m);
        float s = p0 + p1;
#pragma unroll
        for (int o = 16; o; o >>= 1) s += __shfl_xor_sync(0xffffffffu, s, o);
        const float inv = 1.0f / s;
        const float a0 = p0 * inv, a1 = p1 * inv;
        s_att[v * 65 + ln]      = a0;
        s_att[v * 65 + ln + 32] = a1;
        if (write_att) {
            float* ap = out_att + (size_t)blk * 4096 + v * 64;
            ap[ln]      = a0;
            ap[ln + 32] = a1;
        }
    }
    __syncthreads();

    // h_prime[v][j] = sum_w att[v][w] * h[w][j], j = quad + 4*i
    const int v2 = tid >> 2, quad = tid & 3;
    float acc[16];
#pragma unroll
    for (int i = 0; i < 16; i++) acc[i] = 0.f;
    for (int w = 0; w < 64; w++) {
        const float av = s_att[v2 * 65 + w];
#pragma unroll
        for (int i = 0; i < 16; i++)
            acc[i] = fmaf(av, s_h[w * 65 + quad + 4 * i], acc[i]);
    }
    // ELU
#pragma unroll
    for (int i = 0; i < 16; i++)
        acc[i] = (acc[i] > 0.f) ? acc[i] : (__expf(acc[i]) - 1.0f);

    __syncthreads();                 // everyone done reading s_att
#pragma unroll
    for (int i = 0; i < 16; i++) s_att[v2 * 65 + quad + 4 * i] = acc[i];
    __syncthreads();

    float* op = out_elu + (size_t)blk * 4096;
    for (int idx = tid; idx < 4096; idx += 256)
        op[idx] = s_att[(idx >> 6) * 65 + (idx & 63)];
}

// ---------------------------------------------------------------------------
extern "C" void kernel_launch(void* const* d_in, const int* in_sizes, int n_in,
                              void* d_out, int out_size)
{
    const float* inp = (const float*)d_in[0];   // [16,12,64,64]
    // d_in[1] = adj — dead code in the reference
    const float* W   = (const float*)d_in[2];   // [64,64]
    const float* a   = (const float*)d_in[3];   // [128,1]
    float* out = (float*)d_out;

    const int elu_elems = NB * TT * NN * OO;    // 786432
    const int write_att = (out_size >= 2 * elu_elems) ? 1 : 0;
    float* out_att = out + elu_elems;

    gat_k1<<<NB * TT, 256>>>(inp, W, a);
    gat_k2<<<NB * TT, 256>>>(out, out_att, write_att);
}

// round 2
// speedup vs baseline: 2.3823x; 2.3823x over previous
#include <cuda_runtime.h>
#include <math.h>

#define NB 16
#define TT 12
#define NN 64
#define CC 64
#define OO 64
#define LRELU_ALPHA 0.2f

// Dynamic smem layout (floats): s_W[4096] | s_src[8192]
#define DYN_SMEM_BYTES ((4096 + 8192) * 4)

__global__ __launch_bounds__(256) void gat_fused(
    const float* __restrict__ inp,   // [NB,TT,NN,CC]
    const float* __restrict__ W,     // [CC,OO] row-major
    const float* __restrict__ a,     // [2*OO]
    float* __restrict__ out_elu,     // [NB,TT,NN,OO]
    float* __restrict__ out_att,     // [NB,TT,NN,NN]
    int write_att)
{
    extern __shared__ float smem[];
    float* s_W   = smem;             // 64x64, row-major (as global)
    float* s_src = smem + 4096;      // 128x64 source double-slab (unpadded; rotated access)

    __shared__ float s_a [128];      // a_lo | a_hi
    __shared__ float s_WA[128];      // ti<6: WA1 in [0:64); ti>=6: W@a_lo | W@a_hi
    __shared__ float s_G [256];      // ti<6: G1[128]; ti>=6: G2a[128] | G2b[128]
    __shared__ float s_S [128];      // half rowsums / weighted rowsums (per vb x k)
    __shared__ float s_Q [128];      // SW_lo|SW_hi (ti<6) or elu(q_lo)|elu(q_hi)
    __shared__ float s_p0[64];       // ti<6: a0 per row v ; ti>=6: att2[vb*32+w']
    __shared__ float s_p1[64];       // ti<6: a1 per row v

    const int tid = threadIdx.x;
    const int blk = blockIdx.x;               // n*TT + ti
    const int n = blk / TT, ti = blk - n * TT;
    const bool first = (ti < 6);
    const int src_t = first ? 2 * ti : 2 * (ti - 6);
    const float* src = inp + (size_t)(n * TT + src_t) * 4096;  // two consecutive time slabs
    const float* own = inp + (size_t)blk * 4096;

    // ---- Stage 1: stage W + source double-slab; a; (ti<6) own half rowsums ----
    for (int idx = tid; idx < 4096; idx += 256) s_W[idx] = W[idx];
    for (int idx = tid; idx < 8192; idx += 256) s_src[idx] = src[idx];
    if (tid < 128) s_a[tid] = a[tid];
    if (first && tid < 128) {
        const int hb = tid >> 6, k = tid & 63;          // hb: rows [0,32) vs [32,64)
        const float* p = own + hb * 32 * 64 + k;
        float s = 0.f;
#pragma unroll
        for (int w = 0; w < 32; w++) s += p[w * 64];
        s_S[tid] = s;                                   // s_S[hb*64+k] = sum_w inp[w][k]
    }
    __syncthreads();

    // ---- Stage 2: WA vectors, rotated j (conflict-free row reads of s_W) ----
    if (first) {
        if (tid < 64) {
            const int k = tid;
            float s = 0.f;
#pragma unroll 8
            for (int j0 = 0; j0 < 64; j0++) {
                const int j = (j0 + k) & 63;
                s = fmaf(s_W[k * 64 + j], s_a[j] + s_a[64 + j], s);
            }
            s_WA[k] = s;                                 // (W @ (a_lo+a_hi))[k]
        }
    } else {
        if (tid < 128) {
            const int c = tid >> 6, k = tid & 63;
            const float* av = s_a + c * 64;
            float s = 0.f;
#pragma unroll 8
            for (int j0 = 0; j0 < 64; j0++) {
                const int j = (j0 + k) & 63;
                s = fmaf(s_W[k * 64 + j], av[j], s);
            }
            s_WA[c * 64 + k] = s;                        // W@a_lo | W@a_hi
        }
    }
    __syncthreads();

    // ---- Stage 3: G dots over the 128 source rows (rotated k); ti<6 also SW matvecs ----
    if (first) {
        if (tid < 128) {
            const int u = tid;
            float s = 0.f;
#pragma unroll 8
            for (int k0 = 0; k0 < 64; k0++) {
                const int k = (k0 + u) & 63;
                s = fmaf(s_src[u * 64 + k], s_WA[k], s);
            }
            s_G[u] = s;                                  // G1[u]
        } else {
            const int c = (tid - 128) >> 6, j = tid & 63;
            const float* Sv = s_S + c * 64;
            float s = 0.f;
#pragma unroll 8
            for (int k = 0; k < 64; k++)
                s = fmaf(Sv[k], s_W[k * 64 + j], s);     // column read: conflict-free
            s_Q[c * 64 + j] = s;                         // SW_lo[j] | SW_hi[j]
        }
        __syncthreads();

        // ---- Stage 4a: closed-form softmax per row (2 exps), then outputs ----
        if (tid < 64) {
            const int v = tid, vb = v >> 5;
            float e0 = s_G[vb * 64 + 2 * (v & 31)];      // w <  32
            float e1 = s_G[vb * 64 + 2 * (v & 31) + 1];  // w >= 32
            e0 = (e0 > 0.f) ? e0 : LRELU_ALPHA * e0;
            e1 = (e1 > 0.f) ? e1 : LRELU_ALPHA * e1;
            const float m  = fmaxf(e0, e1);
            const float p0 = __expf(e0 - m), p1 = __expf(e1 - m);
            const float inv = 1.0f / (32.f * (p0 + p1));
            s_p0[v] = p0 * inv;
            s_p1[v] = p1 * inv;
        }
        __syncthreads();

        float* oe = out_elu + (size_t)blk * 4096;
        float* oa = out_att + (size_t)blk * 4096;
        for (int idx = tid; idx < 4096; idx += 256) {
            const int v = idx >> 6, j = idx & 63;
            const float a0 = s_p0[v], a1 = s_p1[v];
            const float hp = fmaf(a0, s_Q[j], a1 * s_Q[64 + j]);
            oe[idx] = (hp > 0.f) ? hp : (__expf(hp) - 1.0f);
            if (write_att) oa[idx] = (j < 32) ? a0 : a1;
        }
    } else {
        // G2a (c=0) and G2b (c=1), 256 threads
        const int c = tid >> 7, u = tid & 127;
        const float* wav = s_WA + c * 64;
        float s = 0.f;
#pragma unroll 8
        for (int k0 = 0; k0 < 64; k0++) {
            const int k = (k0 + u) & 63;
            s = fmaf(s_src[u * 64 + k], wav[k], s);
        }
        s_G[c * 128 + u] = s;
        __syncthreads();

        // ---- Stage 4b: two 32-wide softmaxes (warps 0,1) ----
        const int warp = tid >> 5, ln = tid & 31;
        if (warp < 2) {
            const int vb = warp;
            float e = s_G[vb * 64 + 2 * ln] + s_G[128 + vb * 64 + 2 * ln + 1];
            e = (e > 0.f) ? e : LRELU_ALPHA * e;
            float m = e;
#pragma unroll
            for (int o = 16; o; o >>= 1) m = fmaxf(m, __shfl_xor_sync(0xffffffffu, m, o));
            const float p = __expf(e - m);
            float ssum = p;
#pragma unroll
            for (int o = 16; o; o >>= 1) ssum += __shfl_xor_sync(0xffffffffu, ssum, o);
            s_p0[vb * 32 + ln] = p / (2.f * ssum);       // att value for (vb, w&31)
        }
        __syncthreads();

        // weighted column sums of own slab: wsum[vb][k]
        if (tid < 128) {
            const int vb = tid >> 6, k = tid & 63;
            const float* pw = s_p0 + vb * 32;
            float s2 = 0.f;
#pragma unroll 8
            for (int w = 0; w < 32; w++)
                s2 = fmaf(pw[w], own[w * 64 + k] + own[(w + 32) * 64 + k], s2);
            s_S[tid] = s2;
        }
        __syncthreads();

        // q[vb][j] = wsum[vb] . W[:,j]; fold ELU here (rows identical per vb)
        if (tid < 128) {
            const int vb = tid >> 6, j = tid & 63;
            const float* Sv = s_S + vb * 64;
            float q = 0.f;
#pragma unroll 8
            for (int k = 0; k < 64; k++)
                q = fmaf(Sv[k], s_W[k * 64 + j], q);
            s_Q[vb * 64 + j] = (q > 0.f) ? q : (__expf(q) - 1.0f);
        }
        __syncthreads();

        float* oe = out_elu + (size_t)blk * 4096;
        float* oa = out_att + (size_t)blk * 4096;
        for (int idx = tid; idx < 4096; idx += 256) {
            const int v = idx >> 6, j = idx & 63, vb = v >> 5;
            oe[idx] = s_Q[vb * 64 + j];
            if (write_att) oa[idx] = s_p0[vb * 32 + (j & 31)];
        }
    }
}

extern "C" void kernel_launch(void* const* d_in, const int* in_sizes, int n_in,
                              void* d_out, int out_size)
{
    const float* inp = (const float*)d_in[0];   // [16,12,64,64]
    // d_in[1] = adj — dead in the reference
    const float* W   = (const float*)d_in[2];   // [64,64]
    const float* a   = (const float*)d_in[3];   // [128,1]
    float* out = (float*)d_out;

    const int elu_elems = NB * TT * NN * OO;    // 786432
    const int write_att = (out_size >= 2 * elu_elems) ? 1 : 0;
    float* out_att = out + elu_elems;

    cudaFuncSetAttribute(gat_fused, cudaFuncAttributeMaxDynamicSharedMemorySize,
                         DYN_SMEM_BYTES);
    gat_fused<<<NB * TT, 256, DYN_SMEM_BYTES>>>(inp, W, a, out, out_att, write_att);
}

// round 3
// speedup vs baseline: 3.2064x; 1.3459x over previous
#include <cuda_runtime.h>
#include <math.h>

#define NB 16
#define TT 12
#define LRELU_ALPHA 0.2f

// Dynamic smem (floats): s_W[4096] | s_src[8192] | s_own[4096]
#define DYN_FLOATS (4096 + 8192 + 4096)
#define DYN_SMEM_BYTES (DYN_FLOATS * 4)

__global__ __launch_bounds__(256) void gat_fused(
    const float* __restrict__ inp,   // [NB,TT,64,64]
    const float* __restrict__ W,     // [64,64]
    const float* __restrict__ a,     // [128]
    float* __restrict__ out_elu,     // [NB,TT,64,64]
    float* __restrict__ out_att,     // [NB,TT,64,64]
    int write_att)
{
    extern __shared__ float smem[];
    float* s_W   = smem;             // 64x64
    float* s_src = smem + 4096;      // 128x64 (two source time slabs)
    float* s_own = smem + 12288;     // 64x64 (own time slab)

    __shared__ __align__(16) float s_a [128];
    __shared__ __align__(16) float s_WA[128];
    __shared__ __align__(16) float s_G [256];
    __shared__ __align__(16) float s_S [128];
    __shared__ __align__(16) float s_Q [128];
    __shared__ __align__(16) float s_p0[64];
    __shared__ __align__(16) float s_p1[64];

    const int tid = threadIdx.x;
    const int blk = blockIdx.x;               // n*TT + ti
    const int n = blk / TT, ti = blk - n * TT;
    const bool first = (ti < 6);
    const int src_t = first ? 2 * ti : 2 * (ti - 6);
    const float* src = inp + (size_t)(n * TT + src_t) * 4096;
    const float* own = inp + (size_t)blk * 4096;

    // ---- Stage A: vectorized staging (single exposed latency) ----
    {
        const float4* Wg = (const float4*)W;
        const float4* Sg = (const float4*)src;
        const float4* Og = (const float4*)own;
        float4* Ws = (float4*)s_W;
        float4* Ss = (float4*)s_src;
        float4* Os = (float4*)s_own;
#pragma unroll
        for (int i = 0; i < 4; i++) Ws[tid + i * 256] = Wg[tid + i * 256];
#pragma unroll
        for (int i = 0; i < 8; i++) Ss[tid + i * 256] = Sg[tid + i * 256];
#pragma unroll
        for (int i = 0; i < 4; i++) Os[tid + i * 256] = Og[tid + i * 256];
        if (tid < 128) s_a[tid] = a[tid];
    }
    __syncthreads();

    if (first) {
        // ---- B: WA1 (tid<64) || own half-colsums (tid>=128) ----
        if (tid < 64) {
            const int k = tid;
            float s0 = 0.f, s1 = 0.f;
#pragma unroll 8
            for (int j0 = 0; j0 < 64; j0 += 2) {
                const int ja = (j0 + k) & 63, jb = (j0 + 1 + k) & 63;
                s0 = fmaf(s_W[k * 64 + ja], s_a[ja] + s_a[64 + ja], s0);
                s1 = fmaf(s_W[k * 64 + jb], s_a[jb] + s_a[64 + jb], s1);
            }
            s_WA[k] = s0 + s1;
        } else if (tid >= 128) {
            const int t2 = tid - 128;
            const int hb = t2 >> 6, k = t2 & 63;
            const float* p = s_own + hb * 2048 + k;
            float s0 = 0.f, s1 = 0.f;
#pragma unroll
            for (int w = 0; w < 32; w += 2) {
                s0 += p[w * 64];
                s1 += p[(w + 1) * 64];
            }
            s_S[t2] = s0 + s1;                 // sum over half rows, per column k
        }
        __syncthreads();

        // ---- C: G1 over 128 source rows (tid<128) || SW matvecs (tid>=128) ----
        if (tid < 128) {
            const int u = tid;
            float s0 = 0.f, s1 = 0.f;
#pragma unroll 8
            for (int k0 = 0; k0 < 64; k0 += 2) {
                const int ka = (k0 + u) & 63, kb = (k0 + 1 + u) & 63;
                s0 = fmaf(s_src[u * 64 + ka], s_WA[ka], s0);
                s1 = fmaf(s_src[u * 64 + kb], s_WA[kb], s1);
            }
            s_G[u] = s0 + s1;
        } else {
            const int t2 = tid - 128;
            const int c = t2 >> 6, j = t2 & 63;
            const float* Sv = s_S + c * 64;
            float s0 = 0.f, s1 = 0.f;
#pragma unroll 8
            for (int k = 0; k < 64; k += 2) {
                s0 = fmaf(Sv[k],     s_W[k * 64 + j],       s0);
                s1 = fmaf(Sv[k + 1], s_W[(k + 1) * 64 + j], s1);
            }
            s_Q[c * 64 + j] = s0 + s1;         // SW_lo[j] | SW_hi[j]
        }
        __syncthreads();

        // ---- D: closed-form per-row softmax (2 exps) ----
        if (tid < 64) {
            const int v = tid, vb = v >> 5;
            float e0 = s_G[vb * 64 + 2 * (v & 31)];
            float e1 = s_G[vb * 64 + 2 * (v & 31) + 1];
            e0 = (e0 > 0.f) ? e0 : LRELU_ALPHA * e0;
            e1 = (e1 > 0.f) ? e1 : LRELU_ALPHA * e1;
            const float m  = fmaxf(e0, e1);
            const float p0 = __expf(e0 - m), p1 = __expf(e1 - m);
            const float inv = 1.0f / (32.f * (p0 + p1));
            s_p0[v] = p0 * inv;
            s_p1[v] = p1 * inv;
        }
        __syncthreads();

        // ---- E: vectorized output ----
        float4* oe = (float4*)(out_elu + (size_t)blk * 4096);
        float4* oa = (float4*)(out_att + (size_t)blk * 4096);
        const float4* Qlo = (const float4*)s_Q;
        const float4* Qhi = (const float4*)(s_Q + 64);
#pragma unroll
        for (int i = 0; i < 4; i++) {
            const int idx4 = tid + i * 256;          // over 1024 float4
            const int v = idx4 >> 4, w4 = idx4 & 15; // j = w4*4
            const float a0 = s_p0[v], a1 = s_p1[v];
            const float4 q0 = Qlo[w4], q1 = Qhi[w4];
            float4 r;
            r.x = fmaf(a0, q0.x, a1 * q1.x);
            r.y = fmaf(a0, q0.y, a1 * q1.y);
            r.z = fmaf(a0, q0.z, a1 * q1.z);
            r.w = fmaf(a0, q0.w, a1 * q1.w);
            r.x = (r.x > 0.f) ? r.x : (__expf(r.x) - 1.f);
            r.y = (r.y > 0.f) ? r.y : (__expf(r.y) - 1.f);
            r.z = (r.z > 0.f) ? r.z : (__expf(r.z) - 1.f);
            r.w = (r.w > 0.f) ? r.w : (__expf(r.w) - 1.f);
            oe[idx4] = r;
            if (write_att) {
                const float av = (w4 < 8) ? a0 : a1; // j<32 ?
                oa[idx4] = make_float4(av, av, av, av);
            }
        }
    } else {
        // ---- B: W@a_lo | W@a_hi (tid<128) ----
        if (tid < 128) {
            const int c = tid >> 6, k = tid & 63;
            const float* av = s_a + c * 64;
            float s0 = 0.f, s1 = 0.f;
#pragma unroll 8
            for (int j0 = 0; j0 < 64; j0 += 2) {
                const int ja = (j0 + k) & 63, jb = (j0 + 1 + k) & 63;
                s0 = fmaf(s_W[k * 64 + ja], av[ja], s0);
                s1 = fmaf(s_W[k * 64 + jb], av[jb], s1);
            }
            s_WA[c * 64 + k] = s0 + s1;
        }
        __syncthreads();

        // ---- C: G2a (c=0) / G2b (c=1) over 128 source rows, all 256 threads ----
        {
            const int c = tid >> 7, u = tid & 127;
            const float* wav = s_WA + c * 64;
            float s0 = 0.f, s1 = 0.f;
#pragma unroll 8
            for (int k0 = 0; k0 < 64; k0 += 2) {
                const int ka = (k0 + u) & 63, kb = (k0 + 1 + u) & 63;
                s0 = fmaf(s_src[u * 64 + ka], wav[ka], s0);
                s1 = fmaf(s_src[u * 64 + kb], wav[kb], s1);
            }
            s_G[c * 128 + u] = s0 + s1;
        }
        __syncthreads();

        // ---- D: two 32-wide softmaxes (warps 0,1) ----
        {
            const int warp = tid >> 5, ln = tid & 31;
            if (warp < 2) {
                const int vb = warp;
                float e = s_G[vb * 64 + 2 * ln] + s_G[128 + vb * 64 + 2 * ln + 1];
                e = (e > 0.f) ? e : LRELU_ALPHA * e;
                float m = e;
#pragma unroll
                for (int o = 16; o; o >>= 1) m = fmaxf(m, __shfl_xor_sync(0xffffffffu, m, o));
                const float p = __expf(e - m);
                float ssum = p;
#pragma unroll
                for (int o = 16; o; o >>= 1) ssum += __shfl_xor_sync(0xffffffffu, ssum, o);
                s_p0[vb * 32 + ln] = p / (2.f * ssum);
            }
        }
        __syncthreads();

        // ---- E: weighted column sums of own slab (from smem now) ----
        if (tid < 128) {
            const int vb = tid >> 6, k = tid & 63;
            const float* pw = s_p0 + vb * 32;
            float s0 = 0.f, s1 = 0.f;
#pragma unroll
            for (int w = 0; w < 32; w += 2) {
                s0 = fmaf(pw[w],     s_own[w * 64 + k]       + s_own[(w + 32) * 64 + k], s0);
                s1 = fmaf(pw[w + 1], s_own[(w + 1) * 64 + k] + s_own[(w + 33) * 64 + k], s1);
            }
            s_S[tid] = s0 + s1;
        }
        __syncthreads();

        // ---- F: q[vb][j] = wsum[vb] . W[:,j], fold ELU ----
        if (tid < 128) {
            const int vb = tid >> 6, j = tid & 63;
            const float* Sv = s_S + vb * 64;
            float s0 = 0.f, s1 = 0.f;
#pragma unroll 8
            for (int k = 0; k < 64; k += 2) {
                s0 = fmaf(Sv[k],     s_W[k * 64 + j],       s0);
                s1 = fmaf(Sv[k + 1], s_W[(k + 1) * 64 + j], s1);
            }
            const float q = s0 + s1;
            s_Q[vb * 64 + j] = (q > 0.f) ? q : (__expf(q) - 1.f);
        }
        __syncthreads();

        // ---- G: vectorized output (rows identical within each half) ----
        float4* oe = (float4*)(out_elu + (size_t)blk * 4096);
        float4* oa = (float4*)(out_att + (size_t)blk * 4096);
        const float4* Q4 = (const float4*)s_Q;
        const float4* P4 = (const float4*)s_p0;
#pragma unroll
        for (int i = 0; i < 4; i++) {
            const int idx4 = tid + i * 256;
            const int v = idx4 >> 4, w4 = idx4 & 15;
            const int vb = v >> 5;
            oe[idx4] = Q4[vb * 16 + w4];
            if (write_att) oa[idx4] = P4[vb * 8 + (w4 & 7)];
        }
    }
}

extern "C" void kernel_launch(void* const* d_in, const int* in_sizes, int n_in,
                              void* d_out, int out_size)
{
    const float* inp = (const float*)d_in[0];   // [16,12,64,64]
    // d_in[1] = adj — dead in the reference
    const float* W   = (const float*)d_in[2];   // [64,64]
    const float* a   = (const float*)d_in[3];   // [128,1]
    float* out = (float*)d_out;

    const int elu_elems = NB * TT * 64 * 64;    // 786432
    const int write_att = (out_size >= 2 * elu_elems) ? 1 : 0;
    float* out_att = out + elu_elems;

    static int smem_set = 0;
    if (!smem_set) {
        cudaFuncSetAttribute(gat_fused, cudaFuncAttributeMaxDynamicSharedMemorySize,
                             DYN_SMEM_BYTES);
        smem_set = 1;
    }
    gat_fused<<<NB * TT, 256, DYN_SMEM_BYTES>>>(inp, W, a, out, out_att, write_att);
}

// round 4
// speedup vs baseline: 3.2827x; 1.0238x over previous
#include <cuda_runtime.h>
#include <math.h>

#define NB 16
#define TT 12
#define AL 0.2f   // LeakyReLU slope

// Per (n,s) table: g2a[64] | g2b[64] | SW_lo[64] | SW_hi[64]
__device__ float d_tab[NB * TT * 256];

// ---------------------------------------------------------------------------
// K1: one block per (n,s). Computes the 256-float table from inp[n,s], W, a.
// ---------------------------------------------------------------------------
__global__ __launch_bounds__(256) void gat_k1(
    const float* __restrict__ inp,   // [NB,TT,64,64]
    const float* __restrict__ W,     // [64,64]
    const float* __restrict__ a)     // [128]
{
    __shared__ __align__(16) float s_inp[4096];
    __shared__ __align__(16) float s_W[4096];
    __shared__ __align__(16) float s_a[128], s_WA[128], s_cs[128], s_out[256];

    const int tid = threadIdx.x, blk = blockIdx.x;

    {   // Stage A: vectorized staging
        const float4* Ig = (const float4*)(inp + (size_t)blk * 4096);
        const float4* Wg = (const float4*)W;
        float4* Is = (float4*)s_inp;
        float4* Ws = (float4*)s_W;
#pragma unroll
        for (int i = 0; i < 4; i++) {
            Is[tid + i * 256] = Ig[tid + i * 256];
            Ws[tid + i * 256] = Wg[tid + i * 256];
        }
        if (tid < 128) s_a[tid] = a[tid];
    }
    __syncthreads();

    // Stage B: WA_c[k] = sum_j W[k][j] a_c[j]  (tid<128)  ||  half colsums (tid>=128)
    if (tid < 128) {
        const int c = tid >> 6, k = tid & 63;
        const float* av = s_a + c * 64;
        float s0 = 0.f, s1 = 0.f;
#pragma unroll 8
        for (int j0 = 0; j0 < 64; j0 += 2) {
            const int ja = (j0 + k) & 63, jb = (j0 + 1 + k) & 63;
            s0 = fmaf(s_W[k * 64 + ja], av[ja], s0);
            s1 = fmaf(s_W[k * 64 + jb], av[jb], s1);
        }
        s_WA[c * 64 + k] = s0 + s1;
    } else {
        const int t2 = tid - 128, hb = t2 >> 6, k = t2 & 63;
        const float* p = s_inp + hb * 2048 + k;
        float s0 = 0.f, s1 = 0.f;
#pragma unroll
        for (int w = 0; w < 32; w += 2) { s0 += p[w * 64]; s1 += p[(w + 1) * 64]; }
        s_cs[t2] = s0 + s1;
    }
    __syncthreads();

    // Stage C: g_c[u] = inp[u] . WA_c  (tid<128)  ||  SW_c[j] = cs_c . W[:,j] (tid>=128)
    if (tid < 128) {
        const int c = tid >> 6, u = tid & 63;
        const float* wav = s_WA + c * 64;
        float s0 = 0.f, s1 = 0.f;
#pragma unroll 8
        for (int k0 = 0; k0 < 64; k0 += 2) {
            const int ka = (k0 + u) & 63, kb = (k0 + 1 + u) & 63;
            s0 = fmaf(s_inp[u * 64 + ka], wav[ka], s0);
            s1 = fmaf(s_inp[u * 64 + kb], wav[kb], s1);
        }
        s_out[c * 64 + u] = s0 + s1;                 // g2a | g2b
    } else {
        const int t2 = tid - 128, c = t2 >> 6, j = t2 & 63;
        const float* cs = s_cs + c * 64;
        float s0 = 0.f, s1 = 0.f;
#pragma unroll 8
        for (int k = 0; k < 64; k += 2) {
            s0 = fmaf(cs[k],     s_W[k * 64 + j],       s0);
            s1 = fmaf(cs[k + 1], s_W[(k + 1) * 64 + j], s1);
        }
        s_out[128 + c * 64 + j] = s0 + s1;           // SW_lo | SW_hi
    }
    __syncthreads();

    d_tab[blk * 256 + tid] = s_out[tid];
}

// ---------------------------------------------------------------------------
// K2: two blocks per (n,ti): vb = bid&1 handles output rows [32*vb, 32*vb+32).
// ---------------------------------------------------------------------------
__global__ __launch_bounds__(256) void gat_k2(
    const float* __restrict__ inp,
    const float* __restrict__ W,
    float* __restrict__ out_elu,     // [NB,TT,64,64]
    float* __restrict__ out_att,     // [NB,TT,64,64]
    int write_att)
{
    __shared__ __align__(16) float s_own[4096];
    __shared__ __align__(16) float s_W[4096];
    __shared__ __align__(16) float s_g1[64], s_SW[128];
    __shared__ __align__(16) float s_p0[32], s_p1[32];
    __shared__ __align__(16) float s_att[32], s_wc[64], s_q[64];

    const int tid = threadIdx.x;
    const int bid = blockIdx.x, pair = bid >> 1, vb = bid & 1;
    const int n = pair / TT, ti = pair - n * TT;

    float4* oe4 = (float4*)(out_elu + (size_t)pair * 4096 + vb * 2048);
    float4* oa4 = (float4*)(out_att + (size_t)pair * 4096 + vb * 2048);

    if (ti < 6) {
        // --- table-only path: no inp, no W ---
        const float* tab_src = d_tab + (size_t)(n * TT + 2 * ti + vb) * 256;
        const float* tab_own = d_tab + (size_t)pair * 256 + 128;
        if (tid < 64)             s_g1[tid] = tab_src[tid] + tab_src[64 + tid];
        else if (tid < 192)       s_SW[tid - 64] = tab_own[tid - 64];
        __syncthreads();

        if (tid < 32) {
            float e0 = s_g1[2 * tid], e1 = s_g1[2 * tid + 1];
            e0 = (e0 > 0.f) ? e0 : AL * e0;
            e1 = (e1 > 0.f) ? e1 : AL * e1;
            const float m = fmaxf(e0, e1);
            const float p0 = __expf(e0 - m), p1 = __expf(e1 - m);
            const float inv = 1.f / (32.f * (p0 + p1));
            s_p0[tid] = p0 * inv;
            s_p1[tid] = p1 * inv;
        }
        __syncthreads();

        const float4* Qlo = (const float4*)s_SW;
        const float4* Qhi = (const float4*)(s_SW + 64);
#pragma unroll
        for (int i = 0; i < 2; i++) {
            const int idx4 = tid + i * 256;          // [0,512): 32 rows x 16 float4
            const int vp = idx4 >> 4, w4 = idx4 & 15;
            const float a0 = s_p0[vp], a1 = s_p1[vp];
            const float4 q0 = Qlo[w4], q1 = Qhi[w4];
            float4 r;
            r.x = fmaf(a0, q0.x, a1 * q1.x);
            r.y = fmaf(a0, q0.y, a1 * q1.y);
            r.z = fmaf(a0, q0.z, a1 * q1.z);
            r.w = fmaf(a0, q0.w, a1 * q1.w);
            r.x = (r.x > 0.f) ? r.x : (__expf(r.x) - 1.f);
            r.y = (r.y > 0.f) ? r.y : (__expf(r.y) - 1.f);
            r.z = (r.z > 0.f) ? r.z : (__expf(r.z) - 1.f);
            r.w = (r.w > 0.f) ? r.w : (__expf(r.w) - 1.f);
            oe4[idx4] = r;
            if (write_att) {
                const float av = (w4 < 8) ? a0 : a1;
                oa4[idx4] = make_float4(av, av, av, av);
            }
        }
    } else {
        // --- ti>=6: own slab + W; 2 distinct output rows (per vb just one) ---
        const float* tab = d_tab + (size_t)(n * TT + 2 * (ti - 6) + vb) * 256;
        {
            const float4* Og = (const float4*)(inp + (size_t)pair * 4096);
            const float4* Wg = (const float4*)W;
            float4* Os = (float4*)s_own;
            float4* Ws = (float4*)s_W;
#pragma unroll
            for (int i = 0; i < 4; i++) {
                Os[tid + i * 256] = Og[tid + i * 256];
                Ws[tid + i * 256] = Wg[tid + i * 256];
            }
        }
        // warp 0: softmax over 32 (reads tables straight from global/L2)
        if (tid < 32) {
            float e = tab[2 * tid] + tab[64 + 2 * tid + 1];   // g2a[2w'] + g2b[2w'+1]
            e = (e > 0.f) ? e : AL * e;
            float m = e;
#pragma unroll
            for (int o = 16; o; o >>= 1) m = fmaxf(m, __shfl_xor_sync(0xffffffffu, m, o));
            const float p = __expf(e - m);
            float ss = p;
#pragma unroll
            for (int o = 16; o; o >>= 1) ss += __shfl_xor_sync(0xffffffffu, ss, o);
            s_att[tid] = p / (2.f * ss);
        }
        __syncthreads();

        // weighted colsum over own slab
        if (tid < 64) {
            const int k = tid;
            float s0 = 0.f, s1 = 0.f;
#pragma unroll
            for (int w = 0; w < 32; w += 2) {
                s0 = fmaf(s_att[w],     s_own[w * 64 + k]       + s_own[(w + 32) * 64 + k], s0);
                s1 = fmaf(s_att[w + 1], s_own[(w + 1) * 64 + k] + s_own[(w + 33) * 64 + k], s1);
            }
            s_wc[k] = s0 + s1;
        }
        __syncthreads();

        // q[j] = wc . W[:,j], fold ELU
        if (tid < 64) {
            const int j = tid;
            float s0 = 0.f, s1 = 0.f;
#pragma unroll 8
            for (int k = 0; k < 64; k += 2) {
                s0 = fmaf(s_wc[k],     s_W[k * 64 + j],       s0);
                s1 = fmaf(s_wc[k + 1], s_W[(k + 1) * 64 + j], s1);
            }
            const float q = s0 + s1;
            s_q[j] = (q > 0.f) ? q : (__expf(q) - 1.f);
        }
        __syncthreads();

        const float4* Q4 = (const float4*)s_q;
        const float4* A4 = (const float4*)s_att;
#pragma unroll
        for (int i = 0; i < 2; i++) {
            const int idx4 = tid + i * 256;
            const int w4 = idx4 & 15;
            oe4[idx4] = Q4[w4];
            if (write_att) oa4[idx4] = A4[w4 & 7];
        }
    }
}

// ---------------------------------------------------------------------------
extern "C" void kernel_launch(void* const* d_in, const int* in_sizes, int n_in,
                              void* d_out, int out_size)
{
    const float* inp = (const float*)d_in[0];   // [16,12,64,64]
    // d_in[1] = adj — dead in the reference
    const float* W   = (const float*)d_in[2];   // [64,64]
    const float* a   = (const float*)d_in[3];   // [128,1]
    float* out = (float*)d_out;

    const int elu_elems = NB * TT * 64 * 64;    // 786432
    const int write_att = (out_size >= 2 * elu_elems) ? 1 : 0;
    float* out_att = out + elu_elems;

    gat_k1<<<NB * TT, 256>>>(inp, W, a);
    gat_k2<<<NB * TT * 2, 256>>>(inp, W, out, out_att, write_att);
}

// round 5
// speedup vs baseline: 3.2925x; 1.0030x over previous
#include <cuda_runtime.h>
#include <math.h>

#define NB 16
#define TT 12
#define AL 0.2f   // LeakyReLU slope

// Dynamic smem (floats): s_W[4096] | s_src[4096] | s_own[4096]
#define DYN_BYTES (3 * 4096 * 4)

__global__ __launch_bounds__(256) void gat_one(
    const float* __restrict__ inp,   // [NB,TT,64,64]
    const float* __restrict__ W,     // [64,64]
    const float* __restrict__ a,     // [128]
    float* __restrict__ out_elu,     // [NB,TT,64,64]
    float* __restrict__ out_att,     // [NB,TT,64,64]
    int write_att)
{
    extern __shared__ float sm[];
    float* s_W   = sm;            // 64x64
    float* s_src = sm + 4096;     // source slab (64x64)
    float* s_own = sm + 8192;     // own slab    (64x64)

    __shared__ __align__(16) float s_a [128];
    __shared__ __align__(16) float s_WA[128];   // ti<6: WA1[64]; ti>=6: WAlo|WAhi
    __shared__ __align__(16) float s_cs[128];   // own half colsums (ti<6)
    __shared__ __align__(16) float s_g [128];   // ti<6: g1[64]; ti>=6: g2a|g2b
    __shared__ __align__(16) float s_SW[128];   // SW_lo | SW_hi (ti<6)
    __shared__ __align__(16) float s_p0[32], s_p1[32];   // ti<6 closed-form probs
    __shared__ __align__(16) float s_att[32];   // ti>=6 att over w'
    __shared__ __align__(16) float s_wc[64], s_q[64];

    const int tid  = threadIdx.x;
    const int bid  = blockIdx.x;
    const int pair = bid >> 1, vb = bid & 1;    // pair = n*TT + ti
    const int n = pair / TT, ti = pair - n * TT;
    const bool first = (ti < 6);
    const int src_t = first ? (2 * ti + vb) : (2 * (ti - 6) + vb);

    // ---- Stage A: stage W + source slab + own slab (one exposed latency) ----
    {
        const float4* Wg = (const float4*)W;
        const float4* Sg = (const float4*)(inp + (size_t)(n * TT + src_t) * 4096);
        const float4* Og = (const float4*)(inp + (size_t)pair * 4096);
        float4* Ws = (float4*)s_W;
        float4* Ss = (float4*)s_src;
        float4* Os = (float4*)s_own;
#pragma unroll
        for (int i = 0; i < 4; i++) {
            Ws[tid + i * 256] = Wg[tid + i * 256];
            Ss[tid + i * 256] = Sg[tid + i * 256];
            Os[tid + i * 256] = Og[tid + i * 256];
        }
        if (tid < 128) s_a[tid] = a[tid];
    }
    __syncthreads();

    // ---- Stage B: WA matvec(s)  ||  (ti<6) own half colsums ----
    if (first) {
        if (tid < 64) {
            const int k = tid;
            float s0 = 0.f, s1 = 0.f;
#pragma unroll 8
            for (int j0 = 0; j0 < 64; j0 += 2) {
                const int ja = (j0 + k) & 63, jb = (j0 + 1 + k) & 63;
                s0 = fmaf(s_W[k * 64 + ja], s_a[ja] + s_a[64 + ja], s0);
                s1 = fmaf(s_W[k * 64 + jb], s_a[jb] + s_a[64 + jb], s1);
            }
            s_WA[k] = s0 + s1;                       // W @ (a_lo + a_hi)
        } else if (tid >= 128) {
            const int t2 = tid - 128, hb = t2 >> 6, k = t2 & 63;
            const float* p = s_own + hb * 2048 + k;
            float s0 = 0.f, s1 = 0.f;
#pragma unroll
            for (int w = 0; w < 32; w += 2) { s0 += p[w * 64]; s1 += p[(w + 1) * 64]; }
            s_cs[t2] = s0 + s1;
        }
    } else {
        if (tid < 128) {
            const int c = tid >> 6, k = tid & 63;
            const float* av = s_a + c * 64;
            float s0 = 0.f, s1 = 0.f;
#pragma unroll 8
            for (int j0 = 0; j0 < 64; j0 += 2) {
                const int ja = (j0 + k) & 63, jb = (j0 + 1 + k) & 63;
                s0 = fmaf(s_W[k * 64 + ja], av[ja], s0);
                s1 = fmaf(s_W[k * 64 + jb], av[jb], s1);
            }
            s_WA[c * 64 + k] = s0 + s1;              // W@a_lo | W@a_hi
        }
    }
    __syncthreads();

    // ---- Stage C: g dots over src rows  ||  (ti<6) SW matvecs ----
    if (first) {
        if (tid < 64) {
            const int u = tid;
            float s0 = 0.f, s1 = 0.f;
#pragma unroll 8
            for (int k0 = 0; k0 < 64; k0 += 2) {
                const int ka = (k0 + u) & 63, kb = (k0 + 1 + u) & 63;
                s0 = fmaf(s_src[u * 64 + ka], s_WA[ka], s0);
                s1 = fmaf(s_src[u * 64 + kb], s_WA[kb], s1);
            }
            s_g[u] = s0 + s1;                        // g1[u]
        } else if (tid >= 128) {
            const int t2 = tid - 128, c = t2 >> 6, j = t2 & 63;
            const float* cs = s_cs + c * 64;
            float s0 = 0.f, s1 = 0.f;
#pragma unroll 8
            for (int k = 0; k < 64; k += 2) {
                s0 = fmaf(cs[k],     s_W[k * 64 + j],       s0);
                s1 = fmaf(cs[k + 1], s_W[(k + 1) * 64 + j], s1);
            }
            s_SW[c * 64 + j] = s0 + s1;              // SW_lo | SW_hi
        }
    } else {
        if (tid < 128) {
            const int c = tid >> 6, u = tid & 63;
            const float* wav = s_WA + c * 64;
            float s0 = 0.f, s1 = 0.f;
#pragma unroll 8
            for (int k0 = 0; k0 < 64; k0 += 2) {
                const int ka = (k0 + u) & 63, kb = (k0 + 1 + u) & 63;
                s0 = fmaf(s_src[u * 64 + ka], wav[ka], s0);
                s1 = fmaf(s_src[u * 64 + kb], wav[kb], s1);
            }
            s_g[c * 64 + u] = s0 + s1;               // g2a[u] | g2b[u]
        }
    }
    __syncthreads();

    if (first) {
        // ---- Stage D: closed-form softmax (2 candidate values per row) ----
        if (tid < 32) {
            float e0 = s_g[2 * tid], e1 = s_g[2 * tid + 1];
            e0 = (e0 > 0.f) ? e0 : AL * e0;
            e1 = (e1 > 0.f) ? e1 : AL * e1;
            const float m = fmaxf(e0, e1);
            const float p0 = __expf(e0 - m), p1 = __expf(e1 - m);
            const float inv = 1.f / (32.f * (p0 + p1));
            s_p0[tid] = p0 * inv;
            s_p1[tid] = p1 * inv;
        }
        __syncthreads();

        // ---- Stage E: outputs (32 rows x 64 cols, float4) ----
        float4* oe4 = (float4*)(out_elu + (size_t)pair * 4096 + vb * 2048);
        float4* oa4 = (float4*)(out_att + (size_t)pair * 4096 + vb * 2048);
        const float4* Qlo = (const float4*)s_SW;
        const float4* Qhi = (const float4*)(s_SW + 64);
#pragma unroll
        for (int i = 0; i < 2; i++) {
            const int idx4 = tid + i * 256;          // [0,512)
            const int vp = idx4 >> 4, w4 = idx4 & 15;
            const float a0 = s_p0[vp], a1 = s_p1[vp];
            const float4 q0 = Qlo[w4], q1 = Qhi[w4];
            float4 r;
            r.x = fmaf(a0, q0.x, a1 * q1.x);
            r.y = fmaf(a0, q0.y, a1 * q1.y);
            r.z = fmaf(a0, q0.z, a1 * q1.z);
            r.w = fmaf(a0, q0.w, a1 * q1.w);
            r.x = (r.x > 0.f) ? r.x : (__expf(r.x) - 1.f);
            r.y = (r.y > 0.f) ? r.y : (__expf(r.y) - 1.f);
            r.z = (r.z > 0.f) ? r.z : (__expf(r.z) - 1.f);
            r.w = (r.w > 0.f) ? r.w : (__expf(r.w) - 1.f);
            oe4[idx4] = r;
            if (write_att) {
                const float av = (w4 < 8) ? a0 : a1;
                oa4[idx4] = make_float4(av, av, av, av);
            }
        }
    } else {
        // ---- Stage D: 32-wide softmax (warp 0) ----
        if (tid < 32) {
            float e = s_g[2 * tid] + s_g[64 + 2 * tid + 1];   // g2a[2w'] + g2b[2w'+1]
            e = (e > 0.f) ? e : AL * e;
            float m = e;
#pragma unroll
            for (int o = 16; o; o >>= 1) m = fmaxf(m, __shfl_xor_sync(0xffffffffu, m, o));
            const float p = __expf(e - m);
            float ss = p;
#pragma unroll
            for (int o = 16; o; o >>= 1) ss += __shfl_xor_sync(0xffffffffu, ss, o);
            s_att[tid] = p / (2.f * ss);
        }
        __syncthreads();

        // ---- Stage E: weighted colsum of own slab ----
        if (tid < 64) {
            const int k = tid;
            float s0 = 0.f, s1 = 0.f;
#pragma unroll
            for (int w = 0; w < 32; w += 2) {
                s0 = fmaf(s_att[w],     s_own[w * 64 + k]       + s_own[(w + 32) * 64 + k], s0);
                s1 = fmaf(s_att[w + 1], s_own[(w + 1) * 64 + k] + s_own[(w + 33) * 64 + k], s1);
            }
            s_wc[k] = s0 + s1;
        }
        __syncthreads();

        // ---- Stage F: q[j] = wc . W[:,j], fold ELU ----
        if (tid < 64) {
            const int j = tid;
            float s0 = 0.f, s1 = 0.f;
#pragma unroll 8
            for (int k = 0; k < 64; k += 2) {
                s0 = fmaf(s_wc[k],     s_W[k * 64 + j],       s0);
                s1 = fmaf(s_wc[k + 1], s_W[(k + 1) * 64 + j], s1);
            }
            const float q = s0 + s1;
            s_q[j] = (q > 0.f) ? q : (__expf(q) - 1.f);
        }
        __syncthreads();

        // ---- Stage G: broadcast outputs ----
        float4* oe4 = (float4*)(out_elu + (size_t)pair * 4096 + vb * 2048);
        float4* oa4 = (float4*)(out_att + (size_t)pair * 4096 + vb * 2048);
        const float4* Q4 = (const float4*)s_q;
        const float4* A4 = (const float4*)s_att;
#pragma unroll
        for (int i = 0; i < 2; i++) {
            const int idx4 = tid + i * 256;
            const int w4 = idx4 & 15;
            oe4[idx4] = Q4[w4];
            if (write_att) oa4[idx4] = A4[w4 & 7];
        }
    }
}

extern "C" void kernel_launch(void* const* d_in, const int* in_sizes, int n_in,
                              void* d_out, int out_size)
{
    const float* inp = (const float*)d_in[0];   // [16,12,64,64]
    // d_in[1] = adj — dead in the reference
    const float* W   = (const float*)d_in[2];   // [64,64]
    const float* a   = (const float*)d_in[3];   // [128,1]
    float* out = (float*)d_out;

    const int elu_elems = NB * TT * 64 * 64;    // 786432
    const int write_att = (out_size >= 2 * elu_elems) ? 1 : 0;
    float* out_att = out + elu_elems;

    static int smem_set = 0;
    if (!smem_set) {
        cudaFuncSetAttribute(gat_one, cudaFuncAttributeMaxDynamicSharedMemorySize,
                             DYN_BYTES);
        smem_set = 1;
    }
    gat_one<<<NB * TT * 2, 256, DYN_BYTES>>>(inp, W, a, out, out_att, write_att);
}